// round 2
// baseline (speedup 1.0000x reference)
#include <cuda_runtime.h>
#include <math.h>

#define CC 10
#define N_ITERS 100
#define TOL 1e-3f

static const int BLOCK = 256;
static const int GRID  = 1184;   // 8 * 148 SMs

// Per-block partials: [block][stat], stats 0..9 = sum p, 10..19 = sum p^2, 20..29 = sum log p
__device__ double g_partials[GRID][32];

// ---------------------------------------------------------------------------
// Kernel 1: one pass over x — softmax per row, accumulate column sums.
// ---------------------------------------------------------------------------
__global__ __launch_bounds__(256) void ed_stats(const float* __restrict__ x, int n) {
    float ap [CC];  // sum p
    float ap2[CC];  // sum p^2
    float alp[CC];  // sum log p
#pragma unroll
    for (int i = 0; i < CC; i++) { ap[i] = 0.f; ap2[i] = 0.f; alp[i] = 0.f; }

    const int stride = blockDim.x * gridDim.x;
    for (int r = blockIdx.x * blockDim.x + threadIdx.x; r < n; r += stride) {
        // row r starts at byte offset 40*r -> always 8-byte aligned: use float2
        const float2* row = reinterpret_cast<const float2*>(x) + r * 5;
        float v[CC];
#pragma unroll
        for (int j = 0; j < 5; j++) {
            float2 t = __ldg(row + j);
            v[2 * j] = t.x; v[2 * j + 1] = t.y;
        }
        float mx = v[0];
#pragma unroll
        for (int i = 1; i < CC; i++) mx = fmaxf(mx, v[i]);
        float e[CC];
        float s = 0.f;
#pragma unroll
        for (int i = 0; i < CC; i++) { e[i] = __expf(v[i] - mx); s += e[i]; }
        float inv = 1.0f / s;
        float ls  = __logf(s);
#pragma unroll
        for (int i = 0; i < CC; i++) {
            float p  = e[i] * inv;
            ap [i] += p;
            ap2[i]  = fmaf(p, p, ap2[i]);
            alp[i] += (v[i] - mx) - ls;   // log p, numerically stable
        }
    }

    // intra-warp reduce
#pragma unroll
    for (int i = 0; i < CC; i++) {
#pragma unroll
        for (int o = 16; o > 0; o >>= 1) {
            ap [i] += __shfl_down_sync(0xffffffffu, ap [i], o);
            ap2[i] += __shfl_down_sync(0xffffffffu, ap2[i], o);
            alp[i] += __shfl_down_sync(0xffffffffu, alp[i], o);
        }
    }

    __shared__ float sh[30][8];
    const int lane = threadIdx.x & 31, w = threadIdx.x >> 5;
    if (lane == 0) {
#pragma unroll
        for (int i = 0; i < CC; i++) {
            sh[i     ][w] = ap [i];
            sh[10 + i][w] = ap2[i];
            sh[20 + i][w] = alp[i];
        }
    }
    __syncthreads();
    if (threadIdx.x < 30) {
        double s2 = 0.0;
#pragma unroll
        for (int w2 = 0; w2 < 8; w2++) s2 += (double)sh[threadIdx.x][w2];
        g_partials[blockIdx.x][threadIdx.x] = s2;
    }
}

// ---------------------------------------------------------------------------
// digamma / trigamma (fp32): recurrence to x>=6 + asymptotic series.
// abs err ~1e-7; note the n factor cancels in the Newton step, so this is
// far inside the 1e-3 tolerance.
// ---------------------------------------------------------------------------
__device__ __forceinline__ float digammaf_(float x) {
    float r = 0.f;
    while (x < 6.f) { r -= __fdividef(1.f, x); x += 1.f; }
    float x1 = __fdividef(1.f, x), x2 = x1 * x1;
    float ser = x2 * (0.083333333333f - x2 * (0.0083333333333f - x2 * 0.0039682539683f));
    return r + __logf(x) - 0.5f * x1 - ser;
}
__device__ __forceinline__ float trigammaf_(float x) {
    float r = 0.f;
    while (x < 6.f) { float ix = __fdividef(1.f, x); r += ix * ix; x += 1.f; }
    float x1 = __fdividef(1.f, x), x2 = x1 * x1;
    float tail = 0.16666666667f - x2 * (0.033333333333f - x2 * 0.023809523810f);
    return r + x1 + 0.5f * x2 + x1 * x2 * tail;
}

__device__ __forceinline__ float warp_allreduce_sum(float v) {
#pragma unroll
    for (int o = 16; o > 0; o >>= 1) v += __shfl_xor_sync(0xffffffffu, v, o);
    return v;
}

// ---------------------------------------------------------------------------
// Kernel 2: reduce per-block partials, then Newton iteration over C=10
// components mapped to lanes 0..9 of warp 0.
// ---------------------------------------------------------------------------
__global__ __launch_bounds__(256) void ed_solve(float* __restrict__ out, int n) {
    __shared__ double st[30];
    const int tid = threadIdx.x;

    // 30 stats x 8 threads each (tids 0..239); all 256 threads run the
    // shuffles (inactive ones carry 0) to keep full-mask shfl legal.
    {
        int stat = tid >> 3, j = tid & 7;
        double s = 0.0;
        if (stat < 30) {
#pragma unroll 4
            for (int b = j; b < GRID; b += 8) s += g_partials[b][stat];
        }
        s += __shfl_down_sync(0xffffffffu, s, 4, 8);
        s += __shfl_down_sync(0xffffffffu, s, 2, 8);
        s += __shfl_down_sync(0xffffffffu, s, 1, 8);
        if (stat < 30 && j == 0) st[stat] = s;
    }
    __syncthreads();

    if (tid < 32) {
        const int  lane = tid;
        const bool act  = (lane < CC);
        const float nf  = (float)n;
        const double dn = (double)n;

        float m1  = act ? (float)(st[lane]      / dn) : 0.f;
        float m2  = act ? (float)(st[10 + lane] / dn) : 0.f;
        float lpa = act ? (float)(st[20 + lane] / dn) : 0.f;

        // method-of-moments init: a0 = m1 * mean_C((m1-m2)/(m2-m1^2))
        float ratio = act ? (m1 - m2) / (m2 - m1 * m1) : 0.f;
        float rmean = warp_allreduce_sum(ratio) * 0.1f;
        float a = act ? m1 * rmean : 1.0f;

        float diff = INFINITY;
        int k = 0;
        while (k < N_ITERS && diff >= TOL) {
            float asum = warp_allreduce_sum(act ? a : 0.f);
            float dgs  = digammaf_(asum);
            float g    = (dgs - digammaf_(a) + lpa) * nf;
            float q    = -nf * trigammaf_(a);
            float z    =  nf * trigammaf_(asum);
            float qinv = 1.f / q;
            float num  = warp_allreduce_sum(act ? g * qinv : 0.f);
            float qs   = warp_allreduce_sum(act ? qinv : 0.f);
            float b    = num / (1.f / z + qs);
            float anew = a - (g - b) * qinv;
            diff = warp_allreduce_sum(act ? fabsf(anew - a) : 0.f);
            a = act ? anew : 1.0f;
            k++;
        }
        if (act) out[lane] = a;
    }
}

// ---------------------------------------------------------------------------
extern "C" void kernel_launch(void* const* d_in, const int* in_sizes, int n_in,
                              void* d_out, int out_size) {
    const float* x = (const float*)d_in[0];
    const int n = in_sizes[0] / CC;   // 2,000,000 rows
    ed_stats<<<GRID, BLOCK>>>(x, n);
    ed_solve<<<1, 256>>>((float*)d_out, n);
}

// round 3
// speedup vs baseline: 1.0051x; 1.0051x over previous
#include <cuda_runtime.h>
#include <math.h>

#define CC 10
#define N_ITERS 100
#define TOL 1e-3f

static const int BLOCK = 256;
static const int GRID  = 1184;   // 8 * 148 SMs

// Per-block partials: [block][stat], stats 0..9 = sum p, 10..19 = sum p^2, 20..29 = sum log p
__device__ double g_partials[GRID][32];

// ---------------------------------------------------------------------------
// Kernel 1: one pass over x — softmax per row, accumulate column sums.
// (Unchanged: measured ~8.6us, at the HBM roofline for 80MB.)
// ---------------------------------------------------------------------------
__global__ __launch_bounds__(256) void ed_stats(const float* __restrict__ x, int n) {
    float ap [CC];  // sum p
    float ap2[CC];  // sum p^2
    float alp[CC];  // sum log p
#pragma unroll
    for (int i = 0; i < CC; i++) { ap[i] = 0.f; ap2[i] = 0.f; alp[i] = 0.f; }

    const int stride = blockDim.x * gridDim.x;
    for (int r = blockIdx.x * blockDim.x + threadIdx.x; r < n; r += stride) {
        const float2* row = reinterpret_cast<const float2*>(x) + r * 5;
        float v[CC];
#pragma unroll
        for (int j = 0; j < 5; j++) {
            float2 t = __ldg(row + j);
            v[2 * j] = t.x; v[2 * j + 1] = t.y;
        }
        float mx = v[0];
#pragma unroll
        for (int i = 1; i < CC; i++) mx = fmaxf(mx, v[i]);
        float e[CC];
        float s = 0.f;
#pragma unroll
        for (int i = 0; i < CC; i++) { e[i] = __expf(v[i] - mx); s += e[i]; }
        float inv = 1.0f / s;
        float ls  = __logf(s);
#pragma unroll
        for (int i = 0; i < CC; i++) {
            float p  = e[i] * inv;
            ap [i] += p;
            ap2[i]  = fmaf(p, p, ap2[i]);
            alp[i] += (v[i] - mx) - ls;
        }
    }

#pragma unroll
    for (int i = 0; i < CC; i++) {
#pragma unroll
        for (int o = 16; o > 0; o >>= 1) {
            ap [i] += __shfl_down_sync(0xffffffffu, ap [i], o);
            ap2[i] += __shfl_down_sync(0xffffffffu, ap2[i], o);
            alp[i] += __shfl_down_sync(0xffffffffu, alp[i], o);
        }
    }

    __shared__ float sh[30][8];
    const int lane = threadIdx.x & 31, w = threadIdx.x >> 5;
    if (lane == 0) {
#pragma unroll
        for (int i = 0; i < CC; i++) {
            sh[i     ][w] = ap [i];
            sh[10 + i][w] = ap2[i];
            sh[20 + i][w] = alp[i];
        }
    }
    __syncthreads();
    if (threadIdx.x < 30) {
        double s2 = 0.0;
#pragma unroll
        for (int w2 = 0; w2 < 8; w2++) s2 += (double)sh[threadIdx.x][w2];
        g_partials[blockIdx.x][threadIdx.x] = s2;
    }
}

// ---------------------------------------------------------------------------
// Fused branchless digamma + trigamma.
// Unconditional shift x -> x+6 (6 INDEPENDENT MUFU reciprocals, shared
// between psi and psi'), then asymptotic series at y >= 6 (abs err ~3e-9).
// No data-dependent loop => fixed ~150cyc latency with full ILP.
// ---------------------------------------------------------------------------
__device__ __forceinline__ void psi01(float x, float& dg, float& tg) {
    float s0 = 0.f, s1 = 0.f;
#pragma unroll
    for (int k = 0; k < 6; k++) {
        float r = __fdividef(1.f, x + (float)k);   // 6 independent MUFUs
        s0 += r;
        s1  = fmaf(r, r, s1);
    }
    float y  = x + 6.f;
    float r  = __fdividef(1.f, y);
    float r2 = r * r;
    // psi(y)  = ln y - 1/(2y) - 1/(12y^2) + 1/(120y^4) - 1/(252y^6)
    dg = __logf(y) - 0.5f * r
       - r2 * (0.0833333333f - r2 * (0.0083333333f - r2 * 0.0039682540f))
       - s0;
    // psi'(y) = 1/y + 1/(2y^2) + 1/(6y^3) - 1/(30y^5) + 1/(42y^7)
    tg = r + 0.5f * r2
       + r * r2 * (0.1666666667f - r2 * (0.0333333333f - r2 * 0.0238095238f))
       + s1;
}

// Paired butterfly allreduce over lanes 0..15 (offsets 8,4,2,1 stay inside a
// 16-lane half). Interleaved for ILP. Lanes 10..15 must carry 0.
__device__ __forceinline__ void allred2_16(float& v1, float& v2) {
#pragma unroll
    for (int o = 8; o > 0; o >>= 1) {
        v1 += __shfl_xor_sync(0xffffffffu, v1, o);
        v2 += __shfl_xor_sync(0xffffffffu, v2, o);
    }
}
__device__ __forceinline__ float allred1_16(float v) {
#pragma unroll
    for (int o = 8; o > 0; o >>= 1) v += __shfl_xor_sync(0xffffffffu, v, o);
    return v;
}

// ---------------------------------------------------------------------------
// Kernel 2: warp-parallel partial reduction (one warp per stat), then Newton
// on warp 0 with components on lanes 0..9.
// ---------------------------------------------------------------------------
__global__ __launch_bounds__(1024) void ed_solve(float* __restrict__ out, int n) {
    __shared__ double st[32];
    const int tid  = threadIdx.x;
    const int w    = tid >> 5;
    const int lane = tid & 31;

    // --- reduction: warp w sums g_partials[*][w]; 37 loads/lane, full MLP ---
    if (w < 30) {
        double s = 0.0;
        for (int b = lane; b < GRID; b += 32) s += g_partials[b][w];
#pragma unroll
        for (int o = 16; o > 0; o >>= 1) s += __shfl_down_sync(0xffffffffu, s, o);
        if (lane == 0) st[w] = s;
    }
    __syncthreads();

    if (w == 0) {
        const bool  act = (lane < CC);
        const double dn = (double)n;

        float m1  = act ? (float)(st[lane]      / dn) : 0.f;
        float m2  = act ? (float)(st[10 + lane] / dn) : 0.f;
        float lpa = act ? (float)(st[20 + lane] / dn) : 0.f;

        // method-of-moments init: a0 = m1 * mean_C((m1-m2)/(m2-m1^2))
        float ratio = act ? (m1 - m2) / (m2 - m1 * m1) : 0.f;
        float rmean = allred1_16(ratio) * 0.1f;
        float a     = act ? m1 * rmean : 0.f;
        float asum  = allred1_16(act ? a : 0.f);
        if (!act) a = 1.0f;   // keep psi01 args benign on idle lanes

        // Newton with rank-1 Hessian inverse. The factor n cancels out of
        // (g - b)/q, so iterate in the n-free form:
        //   g' = dg(asum) - dg(a) + lpa ;  q' = -psi'(a) ;  z' = psi'(asum)
        float diff = INFINITY;
        int k = 0;
        while (k < N_ITERS && diff >= TOL) {
            float dga, tga, dgs, tgs;
            psi01(a, dga, tga);      // independent ->
            psi01(asum, dgs, tgs);   //   overlapped MUFU chains
            float g    = dgs - dga + lpa;
            float qinv = __fdividef(-1.f, tga);
            float num  = act ? g * qinv : 0.f;
            float qs   = act ? qinv     : 0.f;
            allred2_16(num, qs);
            float b    = num / (__fdividef(1.f, tgs) + qs);
            float anew = a - (g - b) * qinv;
            float d    = act ? fabsf(anew - a) : 0.f;
            float an   = act ? anew : 0.f;
            allred2_16(d, an);       // diff and next asum in one pass
            diff = d;
            asum = an;
            a    = act ? anew : 1.0f;
            k++;
        }
        if (act) out[lane] = a;
    }
}

// ---------------------------------------------------------------------------
extern "C" void kernel_launch(void* const* d_in, const int* in_sizes, int n_in,
                              void* d_out, int out_size) {
    const float* x = (const float*)d_in[0];
    const int n = in_sizes[0] / CC;   // 2,000,000 rows
    ed_stats<<<GRID, BLOCK>>>(x, n);
    ed_solve<<<1, 1024>>>((float*)d_out, n);
}